// round 7
// baseline (speedup 1.0000x reference)
#include <cuda_runtime.h>
#include <cuda_fp16.h>
#include <stdint.h>

#define NN 100000
#define NE 3200000
#define NB2 782        // ceil(2*NN/256)

// ---------------- scratch (static device globals; no allocation) ----------------
// rec layout per node: 32 halves (64B, 64B-aligned): [a+be1 (8h) | q (8h) | b (8h) | p (8h)]
__device__ __align__(128) __half g_rec[NN * 32];
__device__ __align__(16) float  g_h[NN * 12];    // [H(8), x(3), pad] fp32
__device__ __align__(16) float  g_s1[NN * 8];    // sum_in  e*p[row]  (mi @ Wn1[0:11])
__device__ __align__(16) float  g_s2[NN * 8];    // sum_out e*q[col]  (mo @ Wn1[11:22])
__device__ int   g_idx[2 * NE];                  // normalized int32: [row(E), col(E)]
__device__ int   g_is64;
__device__ int   g_cnt[2 * NN];                  // [in-deg (by col) | out-deg (by row)]
__device__ int   g_off[2 * NN];                  // exclusive scan; after scatter: end offsets
__device__ int   g_bsum[1024];                   // per-block partials for scan
__device__ int   g_list[2 * NE];                 // [in-lists: other=row | out-lists: other=col]

__constant__ float c_We2[8];
__constant__ float c_be2[1];

// ---------------- math helpers ----------------
__device__ __forceinline__ float ftanh(float x) {
    x = fminf(fmaxf(x, -15.f), 15.f);
    float t = __expf(2.f * x);
    return __fdividef(t - 1.f, t + 1.f);
}
__device__ __forceinline__ float fsig(float x) {
    x = fminf(fmaxf(x, -30.f), 30.f);
    return __fdividef(1.f, 1.f + __expf(-x));
}

// ---------------- index dtype detect ----------------
__global__ void k_detect(const unsigned* raw) {
    int ok = 1;
#pragma unroll
    for (int i = 0; i < 32; i++)
        if (raw[2 * i + 1] != 0u) ok = 0;   // int64 LE: high words all zero
    g_is64 = ok;
}

__global__ void k_zero_cnt() {
    int i = blockIdx.x * blockDim.x + threadIdx.x;
    if (i < 2 * NN) g_cnt[i] = 0;
}

// convert to int32 AND histogram both directions
__global__ void k_convert_hist(const void* raw) {
    int i = blockIdx.x * blockDim.x + threadIdx.x;
    if (i >= 2 * NE) return;
    int v;
    if (g_is64) v = (int)((const long long*)raw)[i];
    else        v = ((const int*)raw)[i];
    g_idx[i] = v;
    if (i >= NE) atomicAdd(&g_cnt[v], 1);        // col -> in-degree
    else         atomicAdd(&g_cnt[NN + v], 1);   // row -> out-degree
}

// ---------------- 2-level exclusive scan over g_cnt[2*NN] -> g_off ----------------
__global__ void k_scan1() {
    __shared__ int s[256];
    int i = blockIdx.x * 256 + threadIdx.x;
    int v = (i < 2 * NN) ? g_cnt[i] : 0;
    s[threadIdx.x] = v;
    __syncthreads();
    for (int d = 1; d < 256; d <<= 1) {
        int t = (threadIdx.x >= d) ? s[threadIdx.x - d] : 0;
        __syncthreads();
        s[threadIdx.x] += t;
        __syncthreads();
    }
    if (i < 2 * NN) g_off[i] = s[threadIdx.x] - v;      // exclusive within block
    if (threadIdx.x == 255) g_bsum[blockIdx.x] = s[255];
}

__global__ void k_scan2() {
    __shared__ int s[1024];
    int t = threadIdx.x;
    int v = (t < NB2) ? g_bsum[t] : 0;
    s[t] = v;
    __syncthreads();
    for (int d = 1; d < 1024; d <<= 1) {
        int u = (t >= d) ? s[t - d] : 0;
        __syncthreads();
        s[t] += u;
        __syncthreads();
    }
    if (t < NB2) g_bsum[t] = s[t] - v;                  // exclusive block offsets
}

__global__ void k_scan3() {
    int i = blockIdx.x * 256 + threadIdx.x;
    if (i < 2 * NN) g_off[i] += g_bsum[blockIdx.x];
}

// scatter both adjacency lists (4B payload each); g_off becomes END offsets
__global__ void k_scatter() {
    int j = blockIdx.x * blockDim.x + threadIdx.x;
    if (j >= NE) return;
    int row = g_idx[j];
    int col = g_idx[NE + j];
    g_list[atomicAdd(&g_off[col], 1)]      = row;   // in-list of col
    g_list[atomicAdd(&g_off[NN + row], 1)] = col;   // out-list of row
}

// ---------------- per-node record builder (fp32 compute -> fp16 store) ----------------
__device__ __forceinline__ void write_rec(
    int v, const float* h, const float* sWe1, const float* sbe1, const float* sWn1)
{
    float a[8], b[8], p[8], q[8];
#pragma unroll
    for (int k = 0; k < 8; k++) { a[k] = sbe1[k]; b[k] = 0.f; p[k] = 0.f; q[k] = 0.f; }
#pragma unroll
    for (int i = 0; i < 11; i++) {
        float hv = h[i];
#pragma unroll
        for (int k = 0; k < 8; k++) {
            a[k] = fmaf(hv, sWe1[i * 8 + k],        a[k]);
            b[k] = fmaf(hv, sWe1[(11 + i) * 8 + k], b[k]);
            p[k] = fmaf(hv, sWn1[i * 8 + k],        p[k]);
            q[k] = fmaf(hv, sWn1[(11 + i) * 8 + k], q[k]);
        }
    }
    __half2* r = (__half2*)(g_rec + v * 32);
    r[0]  = __float22half2_rn(make_float2(a[0], a[1]));
    r[1]  = __float22half2_rn(make_float2(a[2], a[3]));
    r[2]  = __float22half2_rn(make_float2(a[4], a[5]));
    r[3]  = __float22half2_rn(make_float2(a[6], a[7]));
    r[4]  = __float22half2_rn(make_float2(q[0], q[1]));
    r[5]  = __float22half2_rn(make_float2(q[2], q[3]));
    r[6]  = __float22half2_rn(make_float2(q[4], q[5]));
    r[7]  = __float22half2_rn(make_float2(q[6], q[7]));
    r[8]  = __float22half2_rn(make_float2(b[0], b[1]));
    r[9]  = __float22half2_rn(make_float2(b[2], b[3]));
    r[10] = __float22half2_rn(make_float2(b[4], b[5]));
    r[11] = __float22half2_rn(make_float2(b[6], b[7]));
    r[12] = __float22half2_rn(make_float2(p[0], p[1]));
    r[13] = __float22half2_rn(make_float2(p[2], p[3]));
    r[14] = __float22half2_rn(make_float2(p[4], p[5]));
    r[15] = __float22half2_rn(make_float2(p[6], p[7]));
}

// ---------------- init ----------------
__global__ void k_init(const float* __restrict__ x,
                       const float* __restrict__ W_in, const float* __restrict__ b_in,
                       const float* __restrict__ We1,  const float* __restrict__ be1,
                       const float* __restrict__ Wn1)
{
    __shared__ float sWin[24], sbin[8], sWe1[176], sbe1[8], sWn1[176];
    int tid = threadIdx.x;
    if (tid < 24) sWin[tid] = W_in[tid];
    if (tid < 8)  sbin[tid] = b_in[tid];
    if (tid < 8)  sbe1[tid] = be1[tid];
    for (int i = tid; i < 176; i += blockDim.x) sWe1[i] = We1[i];
    for (int i = tid; i < 176; i += blockDim.x) sWn1[i] = Wn1[i];
    __syncthreads();

    int v = blockIdx.x * blockDim.x + tid;
    if (v >= NN) return;

    float xv0 = x[v * 3 + 0], xv1 = x[v * 3 + 1], xv2 = x[v * 3 + 2];
    float h[11];
#pragma unroll
    for (int k = 0; k < 8; k++) {
        float s = sbin[k];
        s = fmaf(xv0, sWin[0 * 8 + k], s);
        s = fmaf(xv1, sWin[1 * 8 + k], s);
        s = fmaf(xv2, sWin[2 * 8 + k], s);
        h[k] = ftanh(s);
    }
    h[8] = xv0; h[9] = xv1; h[10] = xv2;

    float4* hp = (float4*)(g_h + v * 12);
    hp[0] = make_float4(h[0], h[1], h[2],  h[3]);
    hp[1] = make_float4(h[4], h[5], h[6],  h[7]);
    hp[2] = make_float4(h[8], h[9], h[10], 0.f);

    write_rec(v, h, sWe1, sbe1, sWn1);
}

// ---------------- aggregation: warp-per-node gather, both directions, no atomics ----------------
// warp w < NN:  in-pass,  node v=w:     s1[v] = sum_{nb in in-list}  e(a[v],b[nb]) * p[nb]
// warp w >= NN: out-pass, node v=w-NN:  s2[v] = sum_{nb in out-list} e(a[nb],b[v]) * q[nb]
__global__ void __launch_bounds__(256) k_aggr()
{
    int w = (blockIdx.x * blockDim.x + threadIdx.x) >> 5;
    int lane = threadIdx.x & 31;
    if (w >= 2 * NN) return;
    const bool inpass = (w < NN);
    const int v = inpass ? w : w - NN;

    const int end   = g_off[w];
    const int start = end - g_cnt[w];
    const int oOff = inpass ? 16 : 0;   // neighbor half for e:  b (in) / a (out)
    const int mOff = inpass ? 24 : 8;   // message vector:       p (in) / q (out)

    // own half of the edge-net preactivation (broadcast load, all lanes same addr)
    const uint4 ownU = *(const uint4*)(g_rec + v * 32 + (inpass ? 0 : 16));
    const __half2* ownh = (const __half2*)&ownU;

    float acc[8];
#pragma unroll
    for (int k = 0; k < 8; k++) acc[k] = 0.f;

    for (int base = start; base < end; base += 32) {
        int idx = base + lane;
        if (idx < end) {
            int nb = g_list[idx];
            const __half* nrec = g_rec + nb * 32;
            // both loads hit the SAME 128B line (64B-aligned record)
            uint4 oU = *(const uint4*)(nrec + oOff);
            uint4 mU = *(const uint4*)(nrec + mOff);
            const __half2* oh = (const __half2*)&oU;
            const __half2* mh = (const __half2*)&mU;

            float z = c_be2[0];
#pragma unroll
            for (int k = 0; k < 4; k++) {
                float2 t = __half22float2(__hadd2(ownh[k], oh[k]));
                z = fmaf(c_We2[2 * k],     ftanh(t.x), z);
                z = fmaf(c_We2[2 * k + 1], ftanh(t.y), z);
            }
            float e = fsig(z);
#pragma unroll
            for (int k = 0; k < 4; k++) {
                float2 m = __half22float2(mh[k]);
                acc[2 * k]     = fmaf(e, m.x, acc[2 * k]);
                acc[2 * k + 1] = fmaf(e, m.y, acc[2 * k + 1]);
            }
        }
    }

    // warp butterfly reduce all 8 components
#pragma unroll
    for (int off = 16; off; off >>= 1) {
#pragma unroll
        for (int k = 0; k < 8; k++)
            acc[k] += __shfl_xor_sync(0xffffffffu, acc[k], off);
    }

    if (lane == 0) {
        float4* dst = (float4*)((inpass ? g_s1 : g_s2) + v * 8);
        dst[0] = make_float4(acc[0], acc[1], acc[2], acc[3]);
        dst[1] = make_float4(acc[4], acc[5], acc[6], acc[7]);
    }
}

// ---------------- node pass ----------------
__global__ void k_node(const float* __restrict__ We1, const float* __restrict__ be1,
                       const float* __restrict__ Wn1, const float* __restrict__ bn1,
                       const float* __restrict__ Wn2, const float* __restrict__ bn2)
{
    __shared__ float sWe1[176], sbe1[8], sWn1[264], sbn1[8], sWn2[64], sbn2[8];
    int tid = threadIdx.x;
    for (int i = tid; i < 176; i += blockDim.x) sWe1[i] = We1[i];
    for (int i = tid; i < 264; i += blockDim.x) sWn1[i] = Wn1[i];
    for (int i = tid; i < 64;  i += blockDim.x) sWn2[i] = Wn2[i];
    if (tid < 8) { sbe1[tid] = be1[tid]; sbn1[tid] = bn1[tid]; sbn2[tid] = bn2[tid]; }
    __syncthreads();

    int v = blockIdx.x * blockDim.x + tid;
    if (v >= NN) return;

    const float4* hp = (const float4*)(g_h + v * 12);
    float4 h0 = hp[0], h1 = hp[1], h2 = hp[2];
    float h[11] = {h0.x, h0.y, h0.z, h0.w, h1.x, h1.y, h1.z, h1.w, h2.x, h2.y, h2.z};

    const float4* s1p = (const float4*)(g_s1 + v * 8);
    const float4* s2p = (const float4*)(g_s2 + v * 8);
    float4 sa0 = s1p[0], sa1 = s1p[1], sb0 = s2p[0], sb1 = s2p[1];
    float pre[8] = {sa0.x + sb0.x, sa0.y + sb0.y, sa0.z + sb0.z, sa0.w + sb0.w,
                    sa1.x + sb1.x, sa1.y + sb1.y, sa1.z + sb1.z, sa1.w + sb1.w};

#pragma unroll
    for (int k = 0; k < 8; k++) {
        float s = pre[k] + sbn1[k];
#pragma unroll
        for (int i = 0; i < 11; i++)
            s = fmaf(h[i], sWn1[(22 + i) * 8 + k], s);   // M = [mi, mo, h]
        pre[k] = ftanh(s);
    }
    float hn[11];
#pragma unroll
    for (int k = 0; k < 8; k++) {
        float s = sbn2[k];
#pragma unroll
        for (int jj = 0; jj < 8; jj++)
            s = fmaf(pre[jj], sWn2[jj * 8 + k], s);
        hn[k] = ftanh(s);
    }
    hn[8] = h[8]; hn[9] = h[9]; hn[10] = h[10];

    float4* hw = (float4*)(g_h + v * 12);
    hw[0] = make_float4(hn[0], hn[1], hn[2],  hn[3]);
    hw[1] = make_float4(hn[4], hn[5], hn[6],  hn[7]);
    hw[2] = make_float4(hn[8], hn[9], hn[10], 0.f);

    write_rec(v, hn, sWe1, sbe1, sWn1);
}

// ---------------- final edge pass (original order; coalesced output) ----------------
__global__ void k_out(float* __restrict__ out)
{
    int j = blockIdx.x * blockDim.x + threadIdx.x;
    if (j >= NE) return;
    int row = g_idx[j];
    int col = g_idx[NE + j];

    uint4 aU = *(const uint4*)(g_rec + col * 32);       // a
    uint4 bU = *(const uint4*)(g_rec + row * 32 + 16);  // b
    const __half2* ah = (const __half2*)&aU;
    const __half2* bh = (const __half2*)&bU;

    float z = c_be2[0];
#pragma unroll
    for (int k = 0; k < 4; k++) {
        float2 tt = __half22float2(__hadd2(ah[k], bh[k]));
        z = fmaf(c_We2[2 * k],     ftanh(tt.x), z);
        z = fmaf(c_We2[2 * k + 1], ftanh(tt.y), z);
    }
    out[j] = fsig(z);
}

// ---------------- launch ----------------
extern "C" void kernel_launch(void* const* d_in, const int* in_sizes, int n_in,
                              void* d_out, int out_size)
{
    const float* x    = (const float*)d_in[0];
    const void*  eidx = d_in[1];
    const float* W_in = (const float*)d_in[2];
    const float* b_in = (const float*)d_in[3];
    const float* We1  = (const float*)d_in[4];
    const float* be1  = (const float*)d_in[5];
    const float* We2  = (const float*)d_in[6];
    const float* be2  = (const float*)d_in[7];
    const float* Wn1  = (const float*)d_in[8];
    const float* bn1  = (const float*)d_in[9];
    const float* Wn2  = (const float*)d_in[10];
    const float* bn2  = (const float*)d_in[11];
    float* out = (float*)d_out;

    const int TB = 256;
    const int nodeBlocks = (NN + TB - 1) / TB;
    const int edgeBlocks = (NE + TB - 1) / TB;
    const int cvtBlocks  = (2 * NE + TB - 1) / TB;
    const int aggrBlocks = (2 * NN * 32 + TB - 1) / TB;   // warp per node, both dirs

    cudaMemcpyToSymbolAsync(c_We2, We2, 8 * sizeof(float), 0, cudaMemcpyDeviceToDevice, 0);
    cudaMemcpyToSymbolAsync(c_be2, be2, 1 * sizeof(float), 0, cudaMemcpyDeviceToDevice, 0);

    k_detect<<<1, 1>>>((const unsigned*)eidx);
    k_zero_cnt<<<NB2, 256>>>();
    k_convert_hist<<<cvtBlocks, TB>>>(eidx);
    k_scan1<<<NB2, 256>>>();
    k_scan2<<<1, 1024>>>();
    k_scan3<<<NB2, 256>>>();
    k_scatter<<<edgeBlocks, TB>>>();
    k_init<<<nodeBlocks, TB>>>(x, W_in, b_in, We1, be1, Wn1);
    for (int it = 0; it < 3; it++) {
        k_aggr<<<aggrBlocks, TB>>>();
        k_node<<<nodeBlocks, TB>>>(We1, be1, Wn1, bn1, Wn2, bn2);
    }
    k_out<<<edgeBlocks, TB>>>(out);
}

// round 9
// speedup vs baseline: 1.3995x; 1.3995x over previous
#include <cuda_runtime.h>
#include <cuda_fp16.h>
#include <stdint.h>

#define NN 100000
#define NE 3200000

// ---------------- scratch (static device globals; no allocation) ----------------
// rec layout per node: 32 halves (64B, 64B-aligned):
//   chunk0 (32B): [a+be1 (8h) | q (8h)]  -> col side, one 256-bit load
//   chunk1 (32B): [b (8h)     | p (8h)]  -> row side, one 256-bit load
__device__ __align__(128) __half g_rec[NN * 32];
__device__ __align__(16) float  g_h[NN * 12];    // [H(8), x(3), pad] fp32
__device__ __align__(32) float  g_s1[NN * 8];    // sum_in  e*p[row]  (mi @ Wn1[0:11])
__device__ __align__(32) float  g_s2[NN * 8];    // sum_out e*q[col]  (mo @ Wn1[11:22])
__device__ int   g_idx[2 * NE];                  // normalized int32: [row(E), col(E)]
__device__ int   g_is64;

__constant__ float c_We2[8];
__constant__ float c_be2[1];

// ---------------- math helpers ----------------
__device__ __forceinline__ float ftanh(float x) {
    x = fminf(fmaxf(x, -15.f), 15.f);
    float t = __expf(2.f * x);
    return __fdividef(t - 1.f, t + 1.f);
}
__device__ __forceinline__ float fsig(float x) {
    x = fminf(fmaxf(x, -30.f), 30.f);
    return __fdividef(1.f, 1.f + __expf(-x));
}

// 256-bit scattered load (legal on sm_100a); fills 8 x b32 regs
__device__ __forceinline__ void ldg256(const void* p, unsigned* r) {
    asm volatile("ld.global.nc.v8.f32 {%0,%1,%2,%3,%4,%5,%6,%7}, [%8];"
                 : "=r"(r[0]), "=r"(r[1]), "=r"(r[2]), "=r"(r[3]),
                   "=r"(r[4]), "=r"(r[5]), "=r"(r[6]), "=r"(r[7])
                 : "l"(p));
}
// 128-bit fp32 reduction (v8 NOT supported by red on sm_100a)
__device__ __forceinline__ void red_add_v4(float* p, float4 v) {
    asm volatile("red.global.add.v4.f32 [%0], {%1,%2,%3,%4};"
                 :: "l"(p), "f"(v.x), "f"(v.y), "f"(v.z), "f"(v.w) : "memory");
}

// ---------------- index dtype detect + normalize ----------------
__global__ void k_detect(const unsigned* raw) {
    int ok = 1;
#pragma unroll
    for (int i = 0; i < 32; i++)
        if (raw[2 * i + 1] != 0u) ok = 0;   // int64 LE: high words all zero
    g_is64 = ok;
}

__global__ void k_convert(const void* raw) {
    int i = blockIdx.x * blockDim.x + threadIdx.x;
    if (i >= 2 * NE) return;
    if (g_is64) g_idx[i] = (int)((const long long*)raw)[i];
    else        g_idx[i] = ((const int*)raw)[i];
}

// ---------------- per-node record builder (fp32 compute -> fp16 store) ----------------
__device__ __forceinline__ void write_rec_and_clear(
    int v, const float* h, const float* sWe1, const float* sbe1, const float* sWn1)
{
    float a[8], b[8], p[8], q[8];
#pragma unroll
    for (int k = 0; k < 8; k++) { a[k] = sbe1[k]; b[k] = 0.f; p[k] = 0.f; q[k] = 0.f; }
#pragma unroll
    for (int i = 0; i < 11; i++) {
        float hv = h[i];
#pragma unroll
        for (int k = 0; k < 8; k++) {
            a[k] = fmaf(hv, sWe1[i * 8 + k],        a[k]);
            b[k] = fmaf(hv, sWe1[(11 + i) * 8 + k], b[k]);
            p[k] = fmaf(hv, sWn1[i * 8 + k],        p[k]);
            q[k] = fmaf(hv, sWn1[(11 + i) * 8 + k], q[k]);
        }
    }
    __half2* r = (__half2*)(g_rec + v * 32);
    r[0]  = __float22half2_rn(make_float2(a[0], a[1]));
    r[1]  = __float22half2_rn(make_float2(a[2], a[3]));
    r[2]  = __float22half2_rn(make_float2(a[4], a[5]));
    r[3]  = __float22half2_rn(make_float2(a[6], a[7]));
    r[4]  = __float22half2_rn(make_float2(q[0], q[1]));
    r[5]  = __float22half2_rn(make_float2(q[2], q[3]));
    r[6]  = __float22half2_rn(make_float2(q[4], q[5]));
    r[7]  = __float22half2_rn(make_float2(q[6], q[7]));
    r[8]  = __float22half2_rn(make_float2(b[0], b[1]));
    r[9]  = __float22half2_rn(make_float2(b[2], b[3]));
    r[10] = __float22half2_rn(make_float2(b[4], b[5]));
    r[11] = __float22half2_rn(make_float2(b[6], b[7]));
    r[12] = __float22half2_rn(make_float2(p[0], p[1]));
    r[13] = __float22half2_rn(make_float2(p[2], p[3]));
    r[14] = __float22half2_rn(make_float2(p[4], p[5]));
    r[15] = __float22half2_rn(make_float2(p[6], p[7]));

    float4 z = make_float4(0.f, 0.f, 0.f, 0.f);
    float4* s1 = (float4*)(g_s1 + v * 8);
    float4* s2 = (float4*)(g_s2 + v * 8);
    s1[0] = z; s1[1] = z; s2[0] = z; s2[1] = z;
}

// ---------------- init ----------------
__global__ void k_init(const float* __restrict__ x,
                       const float* __restrict__ W_in, const float* __restrict__ b_in,
                       const float* __restrict__ We1,  const float* __restrict__ be1,
                       const float* __restrict__ Wn1)
{
    __shared__ float sWin[24], sbin[8], sWe1[176], sbe1[8], sWn1[176];
    int tid = threadIdx.x;
    if (tid < 24) sWin[tid] = W_in[tid];
    if (tid < 8)  sbin[tid] = b_in[tid];
    if (tid < 8)  sbe1[tid] = be1[tid];
    for (int i = tid; i < 176; i += blockDim.x) sWe1[i] = We1[i];
    for (int i = tid; i < 176; i += blockDim.x) sWn1[i] = Wn1[i];
    __syncthreads();

    int v = blockIdx.x * blockDim.x + tid;
    if (v >= NN) return;

    float xv0 = x[v * 3 + 0], xv1 = x[v * 3 + 1], xv2 = x[v * 3 + 2];
    float h[11];
#pragma unroll
    for (int k = 0; k < 8; k++) {
        float s = sbin[k];
        s = fmaf(xv0, sWin[0 * 8 + k], s);
        s = fmaf(xv1, sWin[1 * 8 + k], s);
        s = fmaf(xv2, sWin[2 * 8 + k], s);
        h[k] = ftanh(s);
    }
    h[8] = xv0; h[9] = xv1; h[10] = xv2;

    float4* hp = (float4*)(g_h + v * 12);
    hp[0] = make_float4(h[0], h[1], h[2],  h[3]);
    hp[1] = make_float4(h[4], h[5], h[6],  h[7]);
    hp[2] = make_float4(h[8], h[9], h[10], 0.f);

    write_rec_and_clear(v, h, sWe1, sbe1, sWn1);
}

// ---------------- edge pass: 2x LDG.256 gather + 4x RED.v4 scatter per edge ----------------
__global__ void k_edge()
{
    int j = blockIdx.x * blockDim.x + threadIdx.x;
    if (j >= NE) return;
    int row = g_idx[j];
    int col = g_idx[NE + j];

    unsigned cU[8], rU[8];
    ldg256(g_rec + col * 32, cU);        // a | q  (one scattered 32B load)
    ldg256(g_rec + row * 32 + 16, rU);   // b | p  (one scattered 32B load)

    const __half2* ah = (const __half2*)cU;        // cU[0..3] = a
    const __half2* qh = (const __half2*)(cU + 4);  // cU[4..7] = q
    const __half2* bh = (const __half2*)rU;        // rU[0..3] = b
    const __half2* ph = (const __half2*)(rU + 4);  // rU[4..7] = p

    float z = c_be2[0];
#pragma unroll
    for (int k = 0; k < 4; k++) {
        float2 t = __half22float2(__hadd2(ah[k], bh[k]));
        z = fmaf(c_We2[2 * k],     ftanh(t.x), z);
        z = fmaf(c_We2[2 * k + 1], ftanh(t.y), z);
    }
    float e = fsig(z);

    float2 p0 = __half22float2(ph[0]), p1 = __half22float2(ph[1]);
    float2 p2 = __half22float2(ph[2]), p3 = __half22float2(ph[3]);
    float2 q0 = __half22float2(qh[0]), q1 = __half22float2(qh[1]);
    float2 q2 = __half22float2(qh[2]), q3 = __half22float2(qh[3]);

    // s1[col] += e * p[row]
    red_add_v4(g_s1 + col * 8,     make_float4(e * p0.x, e * p0.y, e * p1.x, e * p1.y));
    red_add_v4(g_s1 + col * 8 + 4, make_float4(e * p2.x, e * p2.y, e * p3.x, e * p3.y));
    // s2[row] += e * q[col]
    red_add_v4(g_s2 + row * 8,     make_float4(e * q0.x, e * q0.y, e * q1.x, e * q1.y));
    red_add_v4(g_s2 + row * 8 + 4, make_float4(e * q2.x, e * q2.y, e * q3.x, e * q3.y));
}

// ---------------- node pass ----------------
__global__ void k_node(const float* __restrict__ We1, const float* __restrict__ be1,
                       const float* __restrict__ Wn1, const float* __restrict__ bn1,
                       const float* __restrict__ Wn2, const float* __restrict__ bn2)
{
    __shared__ float sWe1[176], sbe1[8], sWn1[264], sbn1[8], sWn2[64], sbn2[8];
    int tid = threadIdx.x;
    for (int i = tid; i < 176; i += blockDim.x) sWe1[i] = We1[i];
    for (int i = tid; i < 264; i += blockDim.x) sWn1[i] = Wn1[i];
    for (int i = tid; i < 64;  i += blockDim.x) sWn2[i] = Wn2[i];
    if (tid < 8) { sbe1[tid] = be1[tid]; sbn1[tid] = bn1[tid]; sbn2[tid] = bn2[tid]; }
    __syncthreads();

    int v = blockIdx.x * blockDim.x + tid;
    if (v >= NN) return;

    const float4* hp = (const float4*)(g_h + v * 12);
    float4 h0 = hp[0], h1 = hp[1], h2 = hp[2];
    float h[11] = {h0.x, h0.y, h0.z, h0.w, h1.x, h1.y, h1.z, h1.w, h2.x, h2.y, h2.z};

    const float4* s1p = (const float4*)(g_s1 + v * 8);
    const float4* s2p = (const float4*)(g_s2 + v * 8);
    float4 sa0 = s1p[0], sa1 = s1p[1], sb0 = s2p[0], sb1 = s2p[1];
    float pre[8] = {sa0.x + sb0.x, sa0.y + sb0.y, sa0.z + sb0.z, sa0.w + sb0.w,
                    sa1.x + sb1.x, sa1.y + sb1.y, sa1.z + sb1.z, sa1.w + sb1.w};

#pragma unroll
    for (int k = 0; k < 8; k++) {
        float s = pre[k] + sbn1[k];
#pragma unroll
        for (int i = 0; i < 11; i++)
            s = fmaf(h[i], sWn1[(22 + i) * 8 + k], s);   // M = [mi, mo, h]
        pre[k] = ftanh(s);
    }
    float hn[11];
#pragma unroll
    for (int k = 0; k < 8; k++) {
        float s = sbn2[k];
#pragma unroll
        for (int jj = 0; jj < 8; jj++)
            s = fmaf(pre[jj], sWn2[jj * 8 + k], s);
        hn[k] = ftanh(s);
    }
    hn[8] = h[8]; hn[9] = h[9]; hn[10] = h[10];

    float4* hw = (float4*)(g_h + v * 12);
    hw[0] = make_float4(hn[0], hn[1], hn[2],  hn[3]);
    hw[1] = make_float4(hn[4], hn[5], hn[6],  hn[7]);
    hw[2] = make_float4(hn[8], hn[9], hn[10], 0.f);

    write_rec_and_clear(v, hn, sWe1, sbe1, sWn1);
}

// ---------------- final edge pass (2 scattered 16B gathers, coalesced write) ----------------
__global__ void k_out(float* __restrict__ out)
{
    int j = blockIdx.x * blockDim.x + threadIdx.x;
    if (j >= NE) return;
    int row = g_idx[j];
    int col = g_idx[NE + j];

    uint4 aU = *(const uint4*)(g_rec + col * 32);       // a
    uint4 bU = *(const uint4*)(g_rec + row * 32 + 16);  // b
    const __half2* ah = (const __half2*)&aU;
    const __half2* bh = (const __half2*)&bU;

    float z = c_be2[0];
#pragma unroll
    for (int k = 0; k < 4; k++) {
        float2 tt = __half22float2(__hadd2(ah[k], bh[k]));
        z = fmaf(c_We2[2 * k],     ftanh(tt.x), z);
        z = fmaf(c_We2[2 * k + 1], ftanh(tt.y), z);
    }
    out[j] = fsig(z);
}

// ---------------- launch ----------------
extern "C" void kernel_launch(void* const* d_in, const int* in_sizes, int n_in,
                              void* d_out, int out_size)
{
    const float* x    = (const float*)d_in[0];
    const void*  eidx = d_in[1];
    const float* W_in = (const float*)d_in[2];
    const float* b_in = (const float*)d_in[3];
    const float* We1  = (const float*)d_in[4];
    const float* be1  = (const float*)d_in[5];
    const float* We2  = (const float*)d_in[6];
    const float* be2  = (const float*)d_in[7];
    const float* Wn1  = (const float*)d_in[8];
    const float* bn1  = (const float*)d_in[9];
    const float* Wn2  = (const float*)d_in[10];
    const float* bn2  = (const float*)d_in[11];
    float* out = (float*)d_out;

    const int TB = 256;
    const int nodeBlocks = (NN + TB - 1) / TB;
    const int edgeBlocks = (NE + TB - 1) / TB;
    const int cvtBlocks  = (2 * NE + TB - 1) / TB;

    cudaMemcpyToSymbolAsync(c_We2, We2, 8 * sizeof(float), 0, cudaMemcpyDeviceToDevice, 0);
    cudaMemcpyToSymbolAsync(c_be2, be2, 1 * sizeof(float), 0, cudaMemcpyDeviceToDevice, 0);

    k_detect<<<1, 1>>>((const unsigned*)eidx);
    k_convert<<<cvtBlocks, TB>>>(eidx);
    k_init<<<nodeBlocks, TB>>>(x, W_in, b_in, We1, be1, Wn1);
    for (int it = 0; it < 3; it++) {
        k_edge<<<edgeBlocks, TB>>>();
        k_node<<<nodeBlocks, TB>>>(We1, be1, Wn1, bn1, Wn2, bn2);
    }
    k_out<<<edgeBlocks, TB>>>(out);
}

// round 10
// speedup vs baseline: 1.8699x; 1.3361x over previous
#include <cuda_runtime.h>
#include <cuda_fp16.h>
#include <stdint.h>

#define NN 100000
#define NE 3200000

// ---------------- scratch (static device globals; no allocation) ----------------
// rec layout per node: 32 halves (64B, 64B-aligned):
//   chunk0 (32B): [a+be1 (8h) | q (8h)]  -> col side, one 256-bit load
//   chunk1 (32B): [b (8h)     | p (8h)]  -> row side, one 256-bit load
__device__ __align__(128) __half g_rec[NN * 32];
__device__ __align__(16) float   g_h[NN * 12];    // [H(8), x(3), pad] fp32
__device__ __align__(16) __half  g_s1[NN * 8];    // fp16 accum: sum_in  e*p[row]
__device__ __align__(16) __half  g_s2[NN * 8];    // fp16 accum: sum_out e*q[col]
__device__ __align__(16) int2    g_idx2[NE];      // packed (row, col) int32
__device__ int   g_is64;

__constant__ float c_We2[8];
__constant__ float c_be2[1];

// ---------------- math helpers ----------------
__device__ __forceinline__ float ftanh(float x) {
    x = fminf(fmaxf(x, -15.f), 15.f);
    float t = __expf(2.f * x);
    return __fdividef(t - 1.f, t + 1.f);
}
__device__ __forceinline__ float fsig(float x) {
    x = fminf(fmaxf(x, -30.f), 30.f);
    return __fdividef(1.f, 1.f + __expf(-x));
}

// 256-bit scattered load (sm_100a); fills 8 x b32 regs
__device__ __forceinline__ void ldg256(const void* p, unsigned* r) {
    asm volatile("ld.global.nc.v8.f32 {%0,%1,%2,%3,%4,%5,%6,%7}, [%8];"
                 : "=r"(r[0]), "=r"(r[1]), "=r"(r[2]), "=r"(r[3]),
                   "=r"(r[4]), "=r"(r[5]), "=r"(r[6]), "=r"(r[7])
                 : "l"(p));
}
// 128-bit packed-half reduction: 8 halves in ONE instruction
__device__ __forceinline__ void red_add_v4_f16x2(__half* p, __half2 v0, __half2 v1,
                                                 __half2 v2, __half2 v3) {
    asm volatile("red.global.add.noftz.v4.f16x2 [%0], {%1,%2,%3,%4};"
                 :: "l"(p),
                    "r"(*(unsigned*)&v0), "r"(*(unsigned*)&v1),
                    "r"(*(unsigned*)&v2), "r"(*(unsigned*)&v3) : "memory");
}

// ---------------- index dtype detect + normalize (packed int2) ----------------
__global__ void k_detect(const unsigned* raw) {
    int ok = 1;
#pragma unroll
    for (int i = 0; i < 32; i++)
        if (raw[2 * i + 1] != 0u) ok = 0;   // int64 LE: high words all zero
    g_is64 = ok;
}

__global__ void k_convert(const void* raw) {
    int j = blockIdx.x * blockDim.x + threadIdx.x;
    if (j >= NE) return;
    int row, col;
    if (g_is64) {
        row = (int)((const long long*)raw)[j];
        col = (int)((const long long*)raw)[NE + j];
    } else {
        row = ((const int*)raw)[j];
        col = ((const int*)raw)[NE + j];
    }
    g_idx2[j] = make_int2(row, col);
}

// ---------------- per-node record builder (fp32 compute -> fp16 store) ----------------
__device__ __forceinline__ void write_rec_and_clear(
    int v, const float* h, const float* sWe1, const float* sbe1, const float* sWn1)
{
    float a[8], b[8], p[8], q[8];
#pragma unroll
    for (int k = 0; k < 8; k++) { a[k] = sbe1[k]; b[k] = 0.f; p[k] = 0.f; q[k] = 0.f; }
#pragma unroll
    for (int i = 0; i < 11; i++) {
        float hv = h[i];
#pragma unroll
        for (int k = 0; k < 8; k++) {
            a[k] = fmaf(hv, sWe1[i * 8 + k],        a[k]);
            b[k] = fmaf(hv, sWe1[(11 + i) * 8 + k], b[k]);
            p[k] = fmaf(hv, sWn1[i * 8 + k],        p[k]);
            q[k] = fmaf(hv, sWn1[(11 + i) * 8 + k], q[k]);
        }
    }
    __half2* r = (__half2*)(g_rec + v * 32);
    r[0]  = __float22half2_rn(make_float2(a[0], a[1]));
    r[1]  = __float22half2_rn(make_float2(a[2], a[3]));
    r[2]  = __float22half2_rn(make_float2(a[4], a[5]));
    r[3]  = __float22half2_rn(make_float2(a[6], a[7]));
    r[4]  = __float22half2_rn(make_float2(q[0], q[1]));
    r[5]  = __float22half2_rn(make_float2(q[2], q[3]));
    r[6]  = __float22half2_rn(make_float2(q[4], q[5]));
    r[7]  = __float22half2_rn(make_float2(q[6], q[7]));
    r[8]  = __float22half2_rn(make_float2(b[0], b[1]));
    r[9]  = __float22half2_rn(make_float2(b[2], b[3]));
    r[10] = __float22half2_rn(make_float2(b[4], b[5]));
    r[11] = __float22half2_rn(make_float2(b[6], b[7]));
    r[12] = __float22half2_rn(make_float2(p[0], p[1]));
    r[13] = __float22half2_rn(make_float2(p[2], p[3]));
    r[14] = __float22half2_rn(make_float2(p[4], p[5]));
    r[15] = __float22half2_rn(make_float2(p[6], p[7]));

    float4 z = make_float4(0.f, 0.f, 0.f, 0.f);
    *(float4*)(g_s1 + v * 8) = z;   // 16B zero = 8 halves
    *(float4*)(g_s2 + v * 8) = z;
}

// ---------------- init ----------------
__global__ void k_init(const float* __restrict__ x,
                       const float* __restrict__ W_in, const float* __restrict__ b_in,
                       const float* __restrict__ We1,  const float* __restrict__ be1,
                       const float* __restrict__ Wn1)
{
    __shared__ float sWin[24], sbin[8], sWe1[176], sbe1[8], sWn1[176];
    int tid = threadIdx.x;
    if (tid < 24) sWin[tid] = W_in[tid];
    if (tid < 8)  sbin[tid] = b_in[tid];
    if (tid < 8)  sbe1[tid] = be1[tid];
    for (int i = tid; i < 176; i += blockDim.x) sWe1[i] = We1[i];
    for (int i = tid; i < 176; i += blockDim.x) sWn1[i] = Wn1[i];
    __syncthreads();

    int v = blockIdx.x * blockDim.x + tid;
    if (v >= NN) return;

    float xv0 = x[v * 3 + 0], xv1 = x[v * 3 + 1], xv2 = x[v * 3 + 2];
    float h[11];
#pragma unroll
    for (int k = 0; k < 8; k++) {
        float s = sbin[k];
        s = fmaf(xv0, sWin[0 * 8 + k], s);
        s = fmaf(xv1, sWin[1 * 8 + k], s);
        s = fmaf(xv2, sWin[2 * 8 + k], s);
        h[k] = ftanh(s);
    }
    h[8] = xv0; h[9] = xv1; h[10] = xv2;

    float4* hp = (float4*)(g_h + v * 12);
    hp[0] = make_float4(h[0], h[1], h[2],  h[3]);
    hp[1] = make_float4(h[4], h[5], h[6],  h[7]);
    hp[2] = make_float4(h[8], h[9], h[10], 0.f);

    write_rec_and_clear(v, h, sWe1, sbe1, sWn1);
}

// ---------------- edge pass: 2x LDG.256 + 2x RED.v4.f16x2 per edge ----------------
__global__ void k_edge()
{
    int j = blockIdx.x * blockDim.x + threadIdx.x;
    if (j >= NE) return;
    int2 rc = g_idx2[j];
    int row = rc.x, col = rc.y;

    unsigned cU[8], rU[8];
    ldg256(g_rec + col * 32, cU);        // a | q  (one scattered 32B load)
    ldg256(g_rec + row * 32 + 16, rU);   // b | p  (one scattered 32B load)

    const __half2* ah = (const __half2*)cU;        // cU[0..3] = a
    const __half2* qh = (const __half2*)(cU + 4);  // cU[4..7] = q
    const __half2* bh = (const __half2*)rU;        // rU[0..3] = b
    const __half2* ph = (const __half2*)(rU + 4);  // rU[4..7] = p

    float z = c_be2[0];
#pragma unroll
    for (int k = 0; k < 4; k++) {
        float2 t = __half22float2(__hadd2(ah[k], bh[k]));
        z = fmaf(c_We2[2 * k],     ftanh(t.x), z);
        z = fmaf(c_We2[2 * k + 1], ftanh(t.y), z);
    }
    float e = fsig(z);
    __half2 e2 = __float2half2_rn(e);

    // s1[col] += e * p[row]   (ONE 128-bit packed-half RED)
    red_add_v4_f16x2(g_s1 + col * 8,
                     __hmul2(e2, ph[0]), __hmul2(e2, ph[1]),
                     __hmul2(e2, ph[2]), __hmul2(e2, ph[3]));
    // s2[row] += e * q[col]   (ONE 128-bit packed-half RED)
    red_add_v4_f16x2(g_s2 + row * 8,
                     __hmul2(e2, qh[0]), __hmul2(e2, qh[1]),
                     __hmul2(e2, qh[2]), __hmul2(e2, qh[3]));
}

// ---------------- node pass ----------------
__global__ void k_node(const float* __restrict__ We1, const float* __restrict__ be1,
                       const float* __restrict__ Wn1, const float* __restrict__ bn1,
                       const float* __restrict__ Wn2, const float* __restrict__ bn2)
{
    __shared__ float sWe1[176], sbe1[8], sWn1[264], sbn1[8], sWn2[64], sbn2[8];
    int tid = threadIdx.x;
    for (int i = tid; i < 176; i += blockDim.x) sWe1[i] = We1[i];
    for (int i = tid; i < 264; i += blockDim.x) sWn1[i] = Wn1[i];
    for (int i = tid; i < 64;  i += blockDim.x) sWn2[i] = Wn2[i];
    if (tid < 8) { sbe1[tid] = be1[tid]; sbn1[tid] = bn1[tid]; sbn2[tid] = bn2[tid]; }
    __syncthreads();

    int v = blockIdx.x * blockDim.x + tid;
    if (v >= NN) return;

    const float4* hp = (const float4*)(g_h + v * 12);
    float4 h0 = hp[0], h1 = hp[1], h2 = hp[2];
    float h[11] = {h0.x, h0.y, h0.z, h0.w, h1.x, h1.y, h1.z, h1.w, h2.x, h2.y, h2.z};

    const __half2* s1h = (const __half2*)(g_s1 + v * 8);
    const __half2* s2h = (const __half2*)(g_s2 + v * 8);
    uint4 s1u = *(const uint4*)s1h;   // 8 halves
    uint4 s2u = *(const uint4*)s2h;
    const __half2* a1 = (const __half2*)&s1u;
    const __half2* a2 = (const __half2*)&s2u;

    float pre[8];
#pragma unroll
    for (int k = 0; k < 4; k++) {
        float2 u = __half22float2(a1[k]);
        float2 w = __half22float2(a2[k]);
        pre[2 * k]     = u.x + w.x;
        pre[2 * k + 1] = u.y + w.y;
    }

#pragma unroll
    for (int k = 0; k < 8; k++) {
        float s = pre[k] + sbn1[k];
#pragma unroll
        for (int i = 0; i < 11; i++)
            s = fmaf(h[i], sWn1[(22 + i) * 8 + k], s);   // M = [mi, mo, h]
        pre[k] = ftanh(s);
    }
    float hn[11];
#pragma unroll
    for (int k = 0; k < 8; k++) {
        float s = sbn2[k];
#pragma unroll
        for (int jj = 0; jj < 8; jj++)
            s = fmaf(pre[jj], sWn2[jj * 8 + k], s);
        hn[k] = ftanh(s);
    }
    hn[8] = h[8]; hn[9] = h[9]; hn[10] = h[10];

    float4* hw = (float4*)(g_h + v * 12);
    hw[0] = make_float4(hn[0], hn[1], hn[2],  hn[3]);
    hw[1] = make_float4(hn[4], hn[5], hn[6],  hn[7]);
    hw[2] = make_float4(hn[8], hn[9], hn[10], 0.f);

    write_rec_and_clear(v, hn, sWe1, sbe1, sWn1);
}

// ---------------- final edge pass (2 scattered 16B gathers, coalesced write) ----------------
__global__ void k_out(float* __restrict__ out)
{
    int j = blockIdx.x * blockDim.x + threadIdx.x;
    if (j >= NE) return;
    int2 rc = g_idx2[j];
    int row = rc.x, col = rc.y;

    uint4 aU = *(const uint4*)(g_rec + col * 32);       // a
    uint4 bU = *(const uint4*)(g_rec + row * 32 + 16);  // b
    const __half2* ah = (const __half2*)&aU;
    const __half2* bh = (const __half2*)&bU;

    float z = c_be2[0];
#pragma unroll
    for (int k = 0; k < 4; k++) {
        float2 tt = __half22float2(__hadd2(ah[k], bh[k]));
        z = fmaf(c_We2[2 * k],     ftanh(tt.x), z);
        z = fmaf(c_We2[2 * k + 1], ftanh(tt.y), z);
    }
    out[j] = fsig(z);
}

// ---------------- launch ----------------
extern "C" void kernel_launch(void* const* d_in, const int* in_sizes, int n_in,
                              void* d_out, int out_size)
{
    const float* x    = (const float*)d_in[0];
    const void*  eidx = d_in[1];
    const float* W_in = (const float*)d_in[2];
    const float* b_in = (const float*)d_in[3];
    const float* We1  = (const float*)d_in[4];
    const float* be1  = (const float*)d_in[5];
    const float* We2  = (const float*)d_in[6];
    const float* be2  = (const float*)d_in[7];
    const float* Wn1  = (const float*)d_in[8];
    const float* bn1  = (const float*)d_in[9];
    const float* Wn2  = (const float*)d_in[10];
    const float* bn2  = (const float*)d_in[11];
    float* out = (float*)d_out;

    const int TB = 256;
    const int nodeBlocks = (NN + TB - 1) / TB;
    const int edgeBlocks = (NE + TB - 1) / TB;

    cudaMemcpyToSymbolAsync(c_We2, We2, 8 * sizeof(float), 0, cudaMemcpyDeviceToDevice, 0);
    cudaMemcpyToSymbolAsync(c_be2, be2, 1 * sizeof(float), 0, cudaMemcpyDeviceToDevice, 0);

    k_detect<<<1, 1>>>((const unsigned*)eidx);
    k_convert<<<edgeBlocks, TB>>>(eidx);
    k_init<<<nodeBlocks, TB>>>(x, W_in, b_in, We1, be1, Wn1);
    for (int it = 0; it < 3; it++) {
        k_edge<<<edgeBlocks, TB>>>();
        k_node<<<nodeBlocks, TB>>>(We1, be1, Wn1, bn1, Wn2, bn2);
    }
    k_out<<<edgeBlocks, TB>>>(out);
}

// round 11
// speedup vs baseline: 1.9498x; 1.0427x over previous
#include <cuda_runtime.h>
#include <cuda_fp16.h>
#include <stdint.h>

#define NN 100000
#define NE 3200000

// ---------------- scratch (static device globals; no allocation) ----------------
// rec layout per node: 32 halves (64B, 64B-aligned):
//   chunk0 (32B): [a+be1 (8h) | q (8h)]  -> col side, one 256-bit load
//   chunk1 (32B): [b (8h)     | p (8h)]  -> row side, one 256-bit load
__device__ __align__(128) __half g_rec[NN * 32];
__device__ __align__(16) float   g_h[NN * 12];    // [H(8), x(3), pad] fp32
__device__ __align__(16) __half  g_s[NN * 8];     // fp16 accum: sum of ALL messages into v
__device__ __align__(16) int2    g_idx2[NE];      // packed (row, col) int32 (built by edge1)
__device__ int   g_is64;

__constant__ float c_We2[8];
__constant__ float c_be2[1];

// ---------------- math helpers ----------------
__device__ __forceinline__ float ftanh(float x) {
    x = fminf(fmaxf(x, -15.f), 15.f);
    float t = __expf(2.f * x);
    return __fdividef(t - 1.f, t + 1.f);
}
__device__ __forceinline__ float fsig(float x) {
    x = fminf(fmaxf(x, -30.f), 30.f);
    return __fdividef(1.f, 1.f + __expf(-x));
}

// 256-bit scattered load (sm_100a); fills 8 x b32 regs
__device__ __forceinline__ void ldg256(const void* p, unsigned* r) {
    asm volatile("ld.global.nc.v8.f32 {%0,%1,%2,%3,%4,%5,%6,%7}, [%8];"
                 : "=r"(r[0]), "=r"(r[1]), "=r"(r[2]), "=r"(r[3]),
                   "=r"(r[4]), "=r"(r[5]), "=r"(r[6]), "=r"(r[7])
                 : "l"(p));
}
// 128-bit packed-half reduction: 8 halves in ONE instruction
__device__ __forceinline__ void red_add_v4_f16x2(__half* p, __half2 v0, __half2 v1,
                                                 __half2 v2, __half2 v3) {
    asm volatile("red.global.add.noftz.v4.f16x2 [%0], {%1,%2,%3,%4};"
                 :: "l"(p),
                    "r"(*(unsigned*)&v0), "r"(*(unsigned*)&v1),
                    "r"(*(unsigned*)&v2), "r"(*(unsigned*)&v3) : "memory");
}

// ---------------- index dtype detect ----------------
__global__ void k_detect(const unsigned* raw) {
    int ok = 1;
#pragma unroll
    for (int i = 0; i < 32; i++)
        if (raw[2 * i + 1] != 0u) ok = 0;   // int64 LE: high words all zero
    g_is64 = ok;
}

// ---------------- shared edge-pass body ----------------
__device__ __forceinline__ void edge_body(int row, int col) {
    unsigned cU[8], rU[8];
    ldg256(g_rec + col * 32, cU);        // a | q  (one scattered 32B load)
    ldg256(g_rec + row * 32 + 16, rU);   // b | p  (one scattered 32B load)

    const __half2* ah = (const __half2*)cU;        // cU[0..3] = a
    const __half2* qh = (const __half2*)(cU + 4);  // cU[4..7] = q
    const __half2* bh = (const __half2*)rU;        // rU[0..3] = b
    const __half2* ph = (const __half2*)(rU + 4);  // rU[4..7] = p

    float z = c_be2[0];
#pragma unroll
    for (int k = 0; k < 4; k++) {
        float2 t = __half22float2(__hadd2(ah[k], bh[k]));
        z = fmaf(c_We2[2 * k],     ftanh(t.x), z);
        z = fmaf(c_We2[2 * k + 1], ftanh(t.y), z);
    }
    float e = fsig(z);
    __half2 e2 = __float2half2_rn(e);

    // node net consumes s1[v] + s2[v], so both directions share ONE accumulator:
    // s[col] += e * p[row]
    red_add_v4_f16x2(g_s + col * 8,
                     __hmul2(e2, ph[0]), __hmul2(e2, ph[1]),
                     __hmul2(e2, ph[2]), __hmul2(e2, ph[3]));
    // s[row] += e * q[col]
    red_add_v4_f16x2(g_s + row * 8,
                     __hmul2(e2, qh[0]), __hmul2(e2, qh[1]),
                     __hmul2(e2, qh[2]), __hmul2(e2, qh[3]));
}

// first edge pass: also converts raw indices -> packed int2 for later passes
__global__ void k_edge_first(const void* __restrict__ raw)
{
    int j = blockIdx.x * blockDim.x + threadIdx.x;
    if (j >= NE) return;
    int row, col;
    if (g_is64) {
        row = (int)((const long long*)raw)[j];
        col = (int)((const long long*)raw)[NE + j];
    } else {
        row = ((const int*)raw)[j];
        col = ((const int*)raw)[NE + j];
    }
    g_idx2[j] = make_int2(row, col);
    edge_body(row, col);
}

// steady-state edge pass: packed indices
__global__ void k_edge()
{
    int j = blockIdx.x * blockDim.x + threadIdx.x;
    if (j >= NE) return;
    int2 rc = g_idx2[j];
    edge_body(rc.x, rc.y);
}

// ---------------- per-node record builder (fp32 compute -> fp16 store) ----------------
__device__ __forceinline__ void write_rec_and_clear(
    int v, const float* h, const float* sWe1, const float* sbe1, const float* sWn1)
{
    float a[8], b[8], p[8], q[8];
#pragma unroll
    for (int k = 0; k < 8; k++) { a[k] = sbe1[k]; b[k] = 0.f; p[k] = 0.f; q[k] = 0.f; }
#pragma unroll
    for (int i = 0; i < 11; i++) {
        float hv = h[i];
#pragma unroll
        for (int k = 0; k < 8; k++) {
            a[k] = fmaf(hv, sWe1[i * 8 + k],        a[k]);
            b[k] = fmaf(hv, sWe1[(11 + i) * 8 + k], b[k]);
            p[k] = fmaf(hv, sWn1[i * 8 + k],        p[k]);
            q[k] = fmaf(hv, sWn1[(11 + i) * 8 + k], q[k]);
        }
    }
    __half2* r = (__half2*)(g_rec + v * 32);
    r[0]  = __float22half2_rn(make_float2(a[0], a[1]));
    r[1]  = __float22half2_rn(make_float2(a[2], a[3]));
    r[2]  = __float22half2_rn(make_float2(a[4], a[5]));
    r[3]  = __float22half2_rn(make_float2(a[6], a[7]));
    r[4]  = __float22half2_rn(make_float2(q[0], q[1]));
    r[5]  = __float22half2_rn(make_float2(q[2], q[3]));
    r[6]  = __float22half2_rn(make_float2(q[4], q[5]));
    r[7]  = __float22half2_rn(make_float2(q[6], q[7]));
    r[8]  = __float22half2_rn(make_float2(b[0], b[1]));
    r[9]  = __float22half2_rn(make_float2(b[2], b[3]));
    r[10] = __float22half2_rn(make_float2(b[4], b[5]));
    r[11] = __float22half2_rn(make_float2(b[6], b[7]));
    r[12] = __float22half2_rn(make_float2(p[0], p[1]));
    r[13] = __float22half2_rn(make_float2(p[2], p[3]));
    r[14] = __float22half2_rn(make_float2(p[4], p[5]));
    r[15] = __float22half2_rn(make_float2(p[6], p[7]));

    *(float4*)(g_s + v * 8) = make_float4(0.f, 0.f, 0.f, 0.f);  // 8 halves
}

// ---------------- init ----------------
__global__ void k_init(const float* __restrict__ x,
                       const float* __restrict__ W_in, const float* __restrict__ b_in,
                       const float* __restrict__ We1,  const float* __restrict__ be1,
                       const float* __restrict__ Wn1)
{
    __shared__ float sWin[24], sbin[8], sWe1[176], sbe1[8], sWn1[176];
    int tid = threadIdx.x;
    if (tid < 24) sWin[tid] = W_in[tid];
    if (tid < 8)  sbin[tid] = b_in[tid];
    if (tid < 8)  sbe1[tid] = be1[tid];
    for (int i = tid; i < 176; i += blockDim.x) sWe1[i] = We1[i];
    for (int i = tid; i < 176; i += blockDim.x) sWn1[i] = Wn1[i];
    __syncthreads();

    int v = blockIdx.x * blockDim.x + tid;
    if (v >= NN) return;

    float xv0 = x[v * 3 + 0], xv1 = x[v * 3 + 1], xv2 = x[v * 3 + 2];
    float h[11];
#pragma unroll
    for (int k = 0; k < 8; k++) {
        float s = sbin[k];
        s = fmaf(xv0, sWin[0 * 8 + k], s);
        s = fmaf(xv1, sWin[1 * 8 + k], s);
        s = fmaf(xv2, sWin[2 * 8 + k], s);
        h[k] = ftanh(s);
    }
    h[8] = xv0; h[9] = xv1; h[10] = xv2;

    float4* hp = (float4*)(g_h + v * 12);
    hp[0] = make_float4(h[0], h[1], h[2],  h[3]);
    hp[1] = make_float4(h[4], h[5], h[6],  h[7]);
    hp[2] = make_float4(h[8], h[9], h[10], 0.f);

    write_rec_and_clear(v, h, sWe1, sbe1, sWn1);
}

// ---------------- node pass ----------------
__global__ void k_node(const float* __restrict__ We1, const float* __restrict__ be1,
                       const float* __restrict__ Wn1, const float* __restrict__ bn1,
                       const float* __restrict__ Wn2, const float* __restrict__ bn2)
{
    __shared__ float sWe1[176], sbe1[8], sWn1[264], sbn1[8], sWn2[64], sbn2[8];
    int tid = threadIdx.x;
    for (int i = tid; i < 176; i += blockDim.x) sWe1[i] = We1[i];
    for (int i = tid; i < 264; i += blockDim.x) sWn1[i] = Wn1[i];
    for (int i = tid; i < 64;  i += blockDim.x) sWn2[i] = Wn2[i];
    if (tid < 8) { sbe1[tid] = be1[tid]; sbn1[tid] = bn1[tid]; sbn2[tid] = bn2[tid]; }
    __syncthreads();

    int v = blockIdx.x * blockDim.x + tid;
    if (v >= NN) return;

    const float4* hp = (const float4*)(g_h + v * 12);
    float4 h0 = hp[0], h1 = hp[1], h2 = hp[2];
    float h[11] = {h0.x, h0.y, h0.z, h0.w, h1.x, h1.y, h1.z, h1.w, h2.x, h2.y, h2.z};

    uint4 su = *(const uint4*)(g_s + v * 8);   // 8 halves: s1[v]+s2[v] combined
    const __half2* a1 = (const __half2*)&su;

    float pre[8];
#pragma unroll
    for (int k = 0; k < 4; k++) {
        float2 u = __half22float2(a1[k]);
        pre[2 * k]     = u.x;
        pre[2 * k + 1] = u.y;
    }

#pragma unroll
    for (int k = 0; k < 8; k++) {
        float s = pre[k] + sbn1[k];
#pragma unroll
        for (int i = 0; i < 11; i++)
            s = fmaf(h[i], sWn1[(22 + i) * 8 + k], s);   // M = [mi, mo, h]
        pre[k] = ftanh(s);
    }
    float hn[11];
#pragma unroll
    for (int k = 0; k < 8; k++) {
        float s = sbn2[k];
#pragma unroll
        for (int jj = 0; jj < 8; jj++)
            s = fmaf(pre[jj], sWn2[jj * 8 + k], s);
        hn[k] = ftanh(s);
    }
    hn[8] = h[8]; hn[9] = h[9]; hn[10] = h[10];

    float4* hw = (float4*)(g_h + v * 12);
    hw[0] = make_float4(hn[0], hn[1], hn[2],  hn[3]);
    hw[1] = make_float4(hn[4], hn[5], hn[6],  hn[7]);
    hw[2] = make_float4(hn[8], hn[9], hn[10], 0.f);

    write_rec_and_clear(v, hn, sWe1, sbe1, sWn1);
}

// ---------------- final edge pass (2 scattered 16B gathers, coalesced write) ----------------
__global__ void k_out(float* __restrict__ out)
{
    int j = blockIdx.x * blockDim.x + threadIdx.x;
    if (j >= NE) return;
    int2 rc = g_idx2[j];
    int row = rc.x, col = rc.y;

    uint4 aU = *(const uint4*)(g_rec + col * 32);       // a
    uint4 bU = *(const uint4*)(g_rec + row * 32 + 16);  // b
    const __half2* ah = (const __half2*)&aU;
    const __half2* bh = (const __half2*)&bU;

    float z = c_be2[0];
#pragma unroll
    for (int k = 0; k < 4; k++) {
        float2 tt = __half22float2(__hadd2(ah[k], bh[k]));
        z = fmaf(c_We2[2 * k],     ftanh(tt.x), z);
        z = fmaf(c_We2[2 * k + 1], ftanh(tt.y), z);
    }
    out[j] = fsig(z);
}

// ---------------- launch ----------------
extern "C" void kernel_launch(void* const* d_in, const int* in_sizes, int n_in,
                              void* d_out, int out_size)
{
    const float* x    = (const float*)d_in[0];
    const void*  eidx = d_in[1];
    const float* W_in = (const float*)d_in[2];
    const float* b_in = (const float*)d_in[3];
    const float* We1  = (const float*)d_in[4];
    const float* be1  = (const float*)d_in[5];
    const float* We2  = (const float*)d_in[6];
    const float* be2  = (const float*)d_in[7];
    const float* Wn1  = (const float*)d_in[8];
    const float* bn1  = (const float*)d_in[9];
    const float* Wn2  = (const float*)d_in[10];
    const float* bn2  = (const float*)d_in[11];
    float* out = (float*)d_out;

    const int TB = 256;
    const int nodeBlocks = (NN + TB - 1) / TB;
    const int edgeBlocks = (NE + TB - 1) / TB;

    cudaMemcpyToSymbolAsync(c_We2, We2, 8 * sizeof(float), 0, cudaMemcpyDeviceToDevice, 0);
    cudaMemcpyToSymbolAsync(c_be2, be2, 1 * sizeof(float), 0, cudaMemcpyDeviceToDevice, 0);

    k_detect<<<1, 1>>>((const unsigned*)eidx);
    k_init<<<nodeBlocks, TB>>>(x, W_in, b_in, We1, be1, Wn1);
    for (int it = 0; it < 3; it++) {
        if (it == 0) k_edge_first<<<edgeBlocks, TB>>>(eidx);   // converts indices inline
        else         k_edge<<<edgeBlocks, TB>>>();
        k_node<<<nodeBlocks, TB>>>(We1, be1, Wn1, bn1, Wn2, bn2);
    }
    k_out<<<edgeBlocks, TB>>>(out);
}